// round 9
// baseline (speedup 1.0000x reference)
#include <cuda_runtime.h>
#include <math.h>

// ---------------------------------------------------------------------------
// K[i,j] = | prod_k cos((x_ik - y_jk)/2) |
//        = | Px_i * Py_j * prod_k (1 + tan(x_ik/2)*tan(y_jk/2)) |
// d==16: single fused kernel; per-CTA tan prologue (MUFU, overlapped),
// 64x64 tile, 4x4 f32x2 per thread, occ-6, IN-PLACE f32x2 fma (no pair movs).
// ---------------------------------------------------------------------------

#define MAXROWS 16384
#define MAXD 64

// scratch for the generic (d != 16) fallback path only
__device__ float g_Tx[MAXD * MAXROWS];
__device__ float g_Ty[MAXD * MAXROWS];
__device__ float g_Px[MAXROWS];
__device__ float g_Py[MAXROWS];

typedef unsigned long long ull;

__device__ __forceinline__ ull f2_mul(ull a, ull b) {
    ull r; asm("mul.rn.f32x2 %0, %1, %2;" : "=l"(r) : "l"(a), "l"(b)); return r;
}
// acc = acc*t + acc, destination pinned to the acc register pair
__device__ __forceinline__ void f2_fma_ip(ull& acc, ull t) {
    asm("fma.rn.f32x2 %0, %0, %1, %0;" : "+l"(acc) : "l"(t));
}
__device__ __forceinline__ ull f2_fma(ull a, ull b, ull c) {
    ull r; asm("fma.rn.f32x2 %0, %1, %2, %3;" : "=l"(r) : "l"(a), "l"(b), "l"(c)); return r;
}
__device__ __forceinline__ ull f2_pack(float lo, float hi) {
    ull r;
    asm("mov.b64 %0, {%1, %2};" : "=l"(r) : "r"(__float_as_uint(lo)), "r"(__float_as_uint(hi)));
    return r;
}
__device__ __forceinline__ void f2_unpack(ull v, float& lo, float& hi) {
    unsigned int a, b;
    asm("mov.b64 {%0, %1}, %2;" : "=r"(a), "=r"(b) : "l"(v));
    lo = __uint_as_float(a); hi = __uint_as_float(b);
}

// --- fused d==16 kernel ----------------------------------------------------
__global__ __launch_bounds__(256, 6) void qk_fused16(float* __restrict__ out,
                                                     const float* __restrict__ x,
                                                     const float* __restrict__ y,
                                                     int n, int m) {
    __shared__ __align__(16) float sTx[16][128];  // rows, duplicated {v,v}
    __shared__ __align__(16) float sTy[16][64];   // cols, planar
    __shared__ __align__(16) float sPx[64];
    __shared__ __align__(16) float sPy[64];

    const int tid = threadIdx.x;
    const int bm0 = blockIdx.y * 64;
    const int bn0 = blockIdx.x * 64;

    // ---- prologue: per-CTA tans + row cos-products (MUFU work) ----
    {
        const int half = tid & 1;          // which 8 wires
        float p = 1.0f;
        if (tid < 128) {
            const int r = tid >> 1;        // local row 0..63
            int gi = bm0 + r; if (gi >= n) gi = n - 1;
            const float4* src = reinterpret_cast<const float4*>(x + gi * 16 + half * 8);
            float4 va = src[0], vb = src[1];
            float vals[8] = {va.x, va.y, va.z, va.w, vb.x, vb.y, vb.z, vb.w};
#pragma unroll
            for (int w = 0; w < 8; w++) {
                float s, c;
                __sincosf(0.5f * vals[w], &s, &c);
                c = (c == 0.0f) ? 1e-30f : c;
                p *= c;
                float t = __fdividef(s, c);
                *reinterpret_cast<float2*>(&sTx[half * 8 + w][2 * r]) = make_float2(t, t);
            }
            p *= __shfl_xor_sync(0xffffffffu, p, 1);
            if (half == 0) sPx[r] = p;
        } else {
            const int r = (tid - 128) >> 1;
            int gj = bn0 + r; if (gj >= m) gj = m - 1;
            const float4* src = reinterpret_cast<const float4*>(y + gj * 16 + half * 8);
            float4 va = src[0], vb = src[1];
            float vals[8] = {va.x, va.y, va.z, va.w, vb.x, vb.y, vb.z, vb.w};
#pragma unroll
            for (int w = 0; w < 8; w++) {
                float s, c;
                __sincosf(0.5f * vals[w], &s, &c);
                c = (c == 0.0f) ? 1e-30f : c;
                p *= c;
                sTy[half * 8 + w][r] = __fdividef(s, c);
            }
            p *= __shfl_xor_sync(0xffffffffu, p, 1);
            if (half == 0) sPy[r] = p;
        }
    }
    __syncthreads();

    // ---- main loop ----
    const int tx = tid & 15;
    const int ty = tid >> 4;
    const int i0 = ty * 4;
    const int j0 = tx * 4;

    const ull ONE2 = f2_pack(1.0f, 1.0f);
    ull a00 = ONE2, a01 = ONE2, a10 = ONE2, a11 = ONE2;
    ull a20 = ONE2, a21 = ONE2, a30 = ONE2, a31 = ONE2;

#pragma unroll 8
    for (int k = 0; k < 16; k++) {
        ulonglong2 yv = *reinterpret_cast<const ulonglong2*>(&sTy[k][j0]);
        ulonglong2 xa = *reinterpret_cast<const ulonglong2*>(&sTx[k][2 * i0]);
        ulonglong2 xb = *reinterpret_cast<const ulonglong2*>(&sTx[k][2 * i0 + 4]);
        f2_fma_ip(a00, f2_mul(xa.x, yv.x));
        f2_fma_ip(a01, f2_mul(xa.x, yv.y));
        f2_fma_ip(a10, f2_mul(xa.y, yv.x));
        f2_fma_ip(a11, f2_mul(xa.y, yv.y));
        f2_fma_ip(a20, f2_mul(xb.x, yv.x));
        f2_fma_ip(a21, f2_mul(xb.x, yv.y));
        f2_fma_ip(a30, f2_mul(xb.y, yv.x));
        f2_fma_ip(a31, f2_mul(xb.y, yv.y));
    }

    // ---- epilogue: scale, abs, store ----
    ulonglong2 pyv = *reinterpret_cast<const ulonglong2*>(&sPy[j0]);
    const bool interior = (bm0 + 63 < n) && (bn0 + 63 < m) && ((m & 3) == 0);
    const int gj = bn0 + j0;

#define QK_EMIT(II, A0, A1)                                                   \
    {                                                                         \
        float px = sPx[i0 + (II)];                                            \
        ull pxp = f2_pack(px, px);                                            \
        ull v0 = f2_mul(f2_mul((A0), pyv.x), pxp);                            \
        ull v1 = f2_mul(f2_mul((A1), pyv.y), pxp);                            \
        float e0, e1, e2, e3;                                                 \
        f2_unpack(v0, e0, e1);                                                \
        f2_unpack(v1, e2, e3);                                                \
        e0 = fabsf(e0); e1 = fabsf(e1); e2 = fabsf(e2); e3 = fabsf(e3);       \
        int gi = bm0 + i0 + (II);                                             \
        if (interior) {                                                       \
            *reinterpret_cast<float4*>(&out[(long long)gi * m + gj]) =        \
                make_float4(e0, e1, e2, e3);                                  \
        } else if (gi < n) {                                                  \
            if (gj + 0 < m) out[(long long)gi * m + gj + 0] = e0;             \
            if (gj + 1 < m) out[(long long)gi * m + gj + 1] = e1;             \
            if (gj + 2 < m) out[(long long)gi * m + gj + 2] = e2;             \
            if (gj + 3 < m) out[(long long)gi * m + gj + 3] = e3;             \
        }                                                                     \
    }

    QK_EMIT(0, a00, a01)
    QK_EMIT(1, a10, a11)
    QK_EMIT(2, a20, a21)
    QK_EMIT(3, a30, a31)
#undef QK_EMIT
}

// --- generic fallback path (runtime d): two kernels ------------------------
__global__ void qk_pre(const float* __restrict__ x, const float* __restrict__ y,
                       int n, int m, int d) {
    int i = blockIdx.x * blockDim.x + threadIdx.x;
    if (i >= n + m) return;
    const float* src = (i < n) ? x : y;
    int r = (i < n) ? i : i - n;
    int N = (i < n) ? n : m;
    float* tab = (i < n) ? g_Tx : g_Ty;
    float p = 1.0f;
    for (int k = 0; k < d; k++) {
        float s, c;
        sincosf(0.5f * src[r * d + k], &s, &c);
        if (c == 0.0f) c = 1e-30f;
        p *= c;
        tab[k * N + r] = s / c;
    }
    if (i < n) g_Px[r] = p; else g_Py[r] = p;
}

__global__ void qk_generic(float* __restrict__ out, int n, int m, int d) {
    int j = blockIdx.x * blockDim.x + threadIdx.x;
    int i = blockIdx.y;
    if (j >= m || i >= n) return;
    float p = 1.0f;
    for (int k = 0; k < d; k++)
        p = fmaf(p * g_Tx[k * n + i], g_Ty[k * m + j], p);
    out[(long long)i * m + j] = fabsf(p * g_Px[i] * g_Py[j]);
}

extern "C" void kernel_launch(void* const* d_in, const int* in_sizes, int n_in,
                              void* d_out, int out_size) {
    const float* x = (const float*)d_in[0];
    const float* y = (const float*)d_in[1];
    float* out = (float*)d_out;

    long long s0 = in_sizes[0], s1 = in_sizes[1];
    int d = (int)(0.5 + sqrt((double)s0 * (double)s1 / (double)out_size));
    if (d < 1) d = 1;
    int n = (int)(s0 / d);
    int m = (int)(s1 / d);

    if (d == 16) {
        dim3 grid((m + 63) / 64, (n + 63) / 64);
        qk_fused16<<<grid, 256>>>(out, x, y, n, m);
    } else {
        int total = n + m;
        qk_pre<<<(total + 255) / 256, 256>>>(x, y, n, m, d);
        dim3 grid((m + 255) / 256, n);
        qk_generic<<<grid, 256>>>(out, n, m, d);
    }
}

// round 13
// speedup vs baseline: 1.3425x; 1.3425x over previous
#include <cuda_runtime.h>
#include <math.h>

// ---------------------------------------------------------------------------
// K[i,j] = | prod_k cos((x_ik - y_jk)/2) |
//        = | Px_i * Py_j * prod_k (1 + tan(x_ik/2)*tan(y_jk/2)) |
// d==16: single fused kernel, 512 threads per CTA, 64x128 tile (4x4 f32x2
// per thread — R8's proven inner loop), per-CTA fast-math tan prologue.
// ---------------------------------------------------------------------------

#define MAXROWS 16384
#define MAXD 64

// scratch for the generic (d != 16) fallback path only
__device__ float g_Tx[MAXD * MAXROWS];
__device__ float g_Ty[MAXD * MAXROWS];
__device__ float g_Px[MAXROWS];
__device__ float g_Py[MAXROWS];

typedef unsigned long long ull;

__device__ __forceinline__ ull f2_mul(ull a, ull b) {
    ull r; asm("mul.rn.f32x2 %0, %1, %2;" : "=l"(r) : "l"(a), "l"(b)); return r;
}
__device__ __forceinline__ ull f2_fma(ull a, ull b, ull c) {
    ull r; asm("fma.rn.f32x2 %0, %1, %2, %3;" : "=l"(r) : "l"(a), "l"(b), "l"(c)); return r;
}
__device__ __forceinline__ ull f2_pack(float lo, float hi) {
    ull r;
    asm("mov.b64 %0, {%1, %2};" : "=l"(r) : "r"(__float_as_uint(lo)), "r"(__float_as_uint(hi)));
    return r;
}
__device__ __forceinline__ void f2_unpack(ull v, float& lo, float& hi) {
    unsigned int a, b;
    asm("mov.b64 {%0, %1}, %2;" : "=r"(a), "=r"(b) : "l"(v));
    lo = __uint_as_float(a); hi = __uint_as_float(b);
}

// --- fused d==16 kernel: 64 rows x 128 cols per 512-thread CTA -------------
__global__ __launch_bounds__(512, 3) void qk_fused16(float* __restrict__ out,
                                                     const float* __restrict__ x,
                                                     const float* __restrict__ y,
                                                     int n, int m) {
    __shared__ __align__(16) float sTx[16][128];  // 64 rows, duplicated {v,v}
    __shared__ __align__(16) float sTy[16][128];  // 128 cols, planar
    __shared__ __align__(16) float sPx[64];
    __shared__ __align__(16) float sPy[128];

    const int tid = threadIdx.x;
    const int bm0 = blockIdx.y * 64;
    const int bn0 = blockIdx.x * 128;

    // ---- prologue ----
    // threads 0..255: x side, 4 threads per row (4 wires each)
    // threads 256..511: y side, 2 threads per col (8 wires each)
    if (tid < 256) {
        const int r = tid >> 2;            // local row 0..63
        const int q = tid & 3;             // wire quarter
        int gi = bm0 + r; if (gi >= n) gi = n - 1;
        float4 v4 = *reinterpret_cast<const float4*>(x + gi * 16 + q * 4);
        float vals[4] = {v4.x, v4.y, v4.z, v4.w};
        float p = 1.0f;
#pragma unroll
        for (int w = 0; w < 4; w++) {
            float s, c;
            __sincosf(0.5f * vals[w], &s, &c);
            c = (c == 0.0f) ? 1e-30f : c;
            p *= c;
            float t = __fdividef(s, c);
            *reinterpret_cast<float2*>(&sTx[q * 4 + w][2 * r]) = make_float2(t, t);
        }
        p *= __shfl_xor_sync(0xffffffffu, p, 1);
        p *= __shfl_xor_sync(0xffffffffu, p, 2);
        if (q == 0) sPx[r] = p;
    } else {
        const int u = tid - 256;
        const int cjj = u >> 1;            // local col 0..127
        const int h = u & 1;               // wire half
        int gj = bn0 + cjj; if (gj >= m) gj = m - 1;
        const float4* src = reinterpret_cast<const float4*>(y + gj * 16 + h * 8);
        float4 va = src[0], vb = src[1];
        float vals[8] = {va.x, va.y, va.z, va.w, vb.x, vb.y, vb.z, vb.w};
        float p = 1.0f;
#pragma unroll
        for (int w = 0; w < 8; w++) {
            float s, c;
            __sincosf(0.5f * vals[w], &s, &c);
            c = (c == 0.0f) ? 1e-30f : c;
            p *= c;
            sTy[h * 8 + w][cjj] = __fdividef(s, c);
        }
        p *= __shfl_xor_sync(0xffffffffu, p, 1);
        if (h == 0) sPy[cjj] = p;
    }
    __syncthreads();

    // ---- main loop (R8's proven core) ----
    const int tx = tid & 31;   // col group: cols j0..j0+3 (32 groups x 4 = 128)
    const int ty = tid >> 5;   // row group: rows i0..i0+3 (16 groups x 4 = 64)
    const int i0 = ty * 4;
    const int j0 = tx * 4;

    const ull ONE2 = f2_pack(1.0f, 1.0f);
    ull a00 = ONE2, a01 = ONE2, a10 = ONE2, a11 = ONE2;
    ull a20 = ONE2, a21 = ONE2, a30 = ONE2, a31 = ONE2;

#pragma unroll
    for (int k = 0; k < 16; k++) {
        ulonglong2 yv = *reinterpret_cast<const ulonglong2*>(&sTy[k][j0]);
        ulonglong2 xa = *reinterpret_cast<const ulonglong2*>(&sTx[k][2 * i0]);
        ulonglong2 xb = *reinterpret_cast<const ulonglong2*>(&sTx[k][2 * i0 + 4]);
        ull t00 = f2_mul(xa.x, yv.x);
        ull t01 = f2_mul(xa.x, yv.y);
        ull t10 = f2_mul(xa.y, yv.x);
        ull t11 = f2_mul(xa.y, yv.y);
        ull t20 = f2_mul(xb.x, yv.x);
        ull t21 = f2_mul(xb.x, yv.y);
        ull t30 = f2_mul(xb.y, yv.x);
        ull t31 = f2_mul(xb.y, yv.y);
        a00 = f2_fma(a00, t00, a00);
        a01 = f2_fma(a01, t01, a01);
        a10 = f2_fma(a10, t10, a10);
        a11 = f2_fma(a11, t11, a11);
        a20 = f2_fma(a20, t20, a20);
        a21 = f2_fma(a21, t21, a21);
        a30 = f2_fma(a30, t30, a30);
        a31 = f2_fma(a31, t31, a31);
    }

    // ---- epilogue: scale, abs, store ----
    ulonglong2 pyv = *reinterpret_cast<const ulonglong2*>(&sPy[j0]);
    const bool interior = (bm0 + 63 < n) && (bn0 + 127 < m) && ((m & 3) == 0);
    const int gj = bn0 + j0;

#define QK_EMIT(II, A0, A1)                                                   \
    {                                                                         \
        float px = sPx[i0 + (II)];                                            \
        ull pxp = f2_pack(px, px);                                            \
        ull v0 = f2_mul(f2_mul((A0), pyv.x), pxp);                            \
        ull v1 = f2_mul(f2_mul((A1), pyv.y), pxp);                            \
        float e0, e1, e2, e3;                                                 \
        f2_unpack(v0, e0, e1);                                                \
        f2_unpack(v1, e2, e3);                                                \
        e0 = fabsf(e0); e1 = fabsf(e1); e2 = fabsf(e2); e3 = fabsf(e3);       \
        int gi = bm0 + i0 + (II);                                             \
        if (interior) {                                                       \
            *reinterpret_cast<float4*>(&out[(long long)gi * m + gj]) =        \
                make_float4(e0, e1, e2, e3);                                  \
        } else if (gi < n) {                                                  \
            if (gj + 0 < m) out[(long long)gi * m + gj + 0] = e0;             \
            if (gj + 1 < m) out[(long long)gi * m + gj + 1] = e1;             \
            if (gj + 2 < m) out[(long long)gi * m + gj + 2] = e2;             \
            if (gj + 3 < m) out[(long long)gi * m + gj + 3] = e3;             \
        }                                                                     \
    }

    QK_EMIT(0, a00, a01)
    QK_EMIT(1, a10, a11)
    QK_EMIT(2, a20, a21)
    QK_EMIT(3, a30, a31)
#undef QK_EMIT
}

// --- generic fallback path (runtime d): two kernels ------------------------
__global__ void qk_pre(const float* __restrict__ x, const float* __restrict__ y,
                       int n, int m, int d) {
    int i = blockIdx.x * blockDim.x + threadIdx.x;
    if (i >= n + m) return;
    const float* src = (i < n) ? x : y;
    int r = (i < n) ? i : i - n;
    int N = (i < n) ? n : m;
    float* tab = (i < n) ? g_Tx : g_Ty;
    float p = 1.0f;
    for (int k = 0; k < d; k++) {
        float s, c;
        sincosf(0.5f * src[r * d + k], &s, &c);
        if (c == 0.0f) c = 1e-30f;
        p *= c;
        tab[k * N + r] = s / c;
    }
    if (i < n) g_Px[r] = p; else g_Py[r] = p;
}

__global__ void qk_generic(float* __restrict__ out, int n, int m, int d) {
    int j = blockIdx.x * blockDim.x + threadIdx.x;
    int i = blockIdx.y;
    if (j >= m || i >= n) return;
    float p = 1.0f;
    for (int k = 0; k < d; k++)
        p = fmaf(p * g_Tx[k * n + i], g_Ty[k * m + j], p);
    out[(long long)i * m + j] = fabsf(p * g_Px[i] * g_Py[j]);
}

extern "C" void kernel_launch(void* const* d_in, const int* in_sizes, int n_in,
                              void* d_out, int out_size) {
    const float* x = (const float*)d_in[0];
    const float* y = (const float*)d_in[1];
    float* out = (float*)d_out;

    long long s0 = in_sizes[0], s1 = in_sizes[1];
    int d = (int)(0.5 + sqrt((double)s0 * (double)s1 / (double)out_size));
    if (d < 1) d = 1;
    int n = (int)(s0 / d);
    int m = (int)(s1 / d);

    if (d == 16) {
        dim3 grid((m + 127) / 128, (n + 63) / 64);
        qk_fused16<<<grid, 512>>>(out, x, y, n, m);
    } else {
        int total = n + m;
        qk_pre<<<(total + 255) / 256, 256>>>(x, y, n, m, d);
        dim3 grid((m + 255) / 256, n);
        qk_generic<<<grid, 256>>>(out, n, m, d);
    }
}

// round 14
// speedup vs baseline: 1.3459x; 1.0025x over previous
#include <cuda_runtime.h>
#include <math.h>

// ---------------------------------------------------------------------------
// K[i,j] = | prod_k cos((x_ik - y_jk)/2) |
//        = | Px_i * Py_j * prod_k (1 + tan(x_ik/2)*tan(y_jk/2)) |
// d==16: single fused kernel; per-CTA tan prologue (MUFU, overlapped),
// 64x64 tile, 4x4 f32x2 per thread. occ-7: 148*7=1036 >= 1024 CTAs
// -> whole grid in ONE wave (kills the 15% straggler-wave tail of occ-6).
// ---------------------------------------------------------------------------

#define MAXROWS 16384
#define MAXD 64

// scratch for the generic (d != 16) fallback path only
__device__ float g_Tx[MAXD * MAXROWS];
__device__ float g_Ty[MAXD * MAXROWS];
__device__ float g_Px[MAXROWS];
__device__ float g_Py[MAXROWS];

typedef unsigned long long ull;

__device__ __forceinline__ ull f2_mul(ull a, ull b) {
    ull r; asm("mul.rn.f32x2 %0, %1, %2;" : "=l"(r) : "l"(a), "l"(b)); return r;
}
__device__ __forceinline__ ull f2_fma(ull a, ull b, ull c) {
    ull r; asm("fma.rn.f32x2 %0, %1, %2, %3;" : "=l"(r) : "l"(a), "l"(b), "l"(c)); return r;
}
__device__ __forceinline__ ull f2_pack(float lo, float hi) {
    ull r;
    asm("mov.b64 %0, {%1, %2};" : "=l"(r) : "r"(__float_as_uint(lo)), "r"(__float_as_uint(hi)));
    return r;
}
__device__ __forceinline__ void f2_unpack(ull v, float& lo, float& hi) {
    unsigned int a, b;
    asm("mov.b64 {%0, %1}, %2;" : "=r"(a), "=r"(b) : "l"(v));
    lo = __uint_as_float(a); hi = __uint_as_float(b);
}

// --- fused d==16 kernel ----------------------------------------------------
__global__ __launch_bounds__(256, 7) void qk_fused16(float* __restrict__ out,
                                                     const float* __restrict__ x,
                                                     const float* __restrict__ y,
                                                     int n, int m) {
    __shared__ __align__(16) float sTx[16][128];  // rows, duplicated {v,v}
    __shared__ __align__(16) float sTy[16][64];   // cols, planar
    __shared__ __align__(16) float sPx[64];
    __shared__ __align__(16) float sPy[64];

    const int tid = threadIdx.x;
    const int bm0 = blockIdx.y * 64;
    const int bn0 = blockIdx.x * 64;

    // ---- prologue: per-CTA tans + row cos-products (MUFU work) ----
    {
        const int half = tid & 1;          // which 8 wires
        float p = 1.0f;
        if (tid < 128) {
            const int r = tid >> 1;        // local row 0..63
            int gi = bm0 + r; if (gi >= n) gi = n - 1;
            const float4* src = reinterpret_cast<const float4*>(x + gi * 16 + half * 8);
            float4 va = src[0], vb = src[1];
            float vals[8] = {va.x, va.y, va.z, va.w, vb.x, vb.y, vb.z, vb.w};
#pragma unroll
            for (int w = 0; w < 8; w++) {
                float s, c;
                __sincosf(0.5f * vals[w], &s, &c);
                c = (c == 0.0f) ? 1e-30f : c;
                p *= c;
                float t = __fdividef(s, c);
                *reinterpret_cast<float2*>(&sTx[half * 8 + w][2 * r]) = make_float2(t, t);
            }
            p *= __shfl_xor_sync(0xffffffffu, p, 1);
            if (half == 0) sPx[r] = p;
        } else {
            const int r = (tid - 128) >> 1;
            int gj = bn0 + r; if (gj >= m) gj = m - 1;
            const float4* src = reinterpret_cast<const float4*>(y + gj * 16 + half * 8);
            float4 va = src[0], vb = src[1];
            float vals[8] = {va.x, va.y, va.z, va.w, vb.x, vb.y, vb.z, vb.w};
#pragma unroll
            for (int w = 0; w < 8; w++) {
                float s, c;
                __sincosf(0.5f * vals[w], &s, &c);
                c = (c == 0.0f) ? 1e-30f : c;
                p *= c;
                sTy[half * 8 + w][r] = __fdividef(s, c);
            }
            p *= __shfl_xor_sync(0xffffffffu, p, 1);
            if (half == 0) sPy[r] = p;
        }
    }
    __syncthreads();

    // ---- main loop ----
    const int tx = tid & 15;
    const int ty = tid >> 4;
    const int i0 = ty * 4;
    const int j0 = tx * 4;

    const ull ONE2 = f2_pack(1.0f, 1.0f);
    ull a00 = ONE2, a01 = ONE2, a10 = ONE2, a11 = ONE2;
    ull a20 = ONE2, a21 = ONE2, a30 = ONE2, a31 = ONE2;

#pragma unroll
    for (int k = 0; k < 16; k++) {
        ulonglong2 yv = *reinterpret_cast<const ulonglong2*>(&sTy[k][j0]);
        ulonglong2 xa = *reinterpret_cast<const ulonglong2*>(&sTx[k][2 * i0]);
        ulonglong2 xb = *reinterpret_cast<const ulonglong2*>(&sTx[k][2 * i0 + 4]);
        ull t00 = f2_mul(xa.x, yv.x);
        ull t01 = f2_mul(xa.x, yv.y);
        ull t10 = f2_mul(xa.y, yv.x);
        ull t11 = f2_mul(xa.y, yv.y);
        ull t20 = f2_mul(xb.x, yv.x);
        ull t21 = f2_mul(xb.x, yv.y);
        ull t30 = f2_mul(xb.y, yv.x);
        ull t31 = f2_mul(xb.y, yv.y);
        a00 = f2_fma(a00, t00, a00);
        a01 = f2_fma(a01, t01, a01);
        a10 = f2_fma(a10, t10, a10);
        a11 = f2_fma(a11, t11, a11);
        a20 = f2_fma(a20, t20, a20);
        a21 = f2_fma(a21, t21, a21);
        a30 = f2_fma(a30, t30, a30);
        a31 = f2_fma(a31, t31, a31);
    }

    // ---- epilogue: scale, abs, store ----
    ulonglong2 pyv = *reinterpret_cast<const ulonglong2*>(&sPy[j0]);
    const bool interior = (bm0 + 63 < n) && (bn0 + 63 < m) && ((m & 3) == 0);
    const int gj = bn0 + j0;

#define QK_EMIT(II, A0, A1)                                                   \
    {                                                                         \
        float px = sPx[i0 + (II)];                                            \
        ull pxp = f2_pack(px, px);                                            \
        ull v0 = f2_mul(f2_mul((A0), pyv.x), pxp);                            \
        ull v1 = f2_mul(f2_mul((A1), pyv.y), pxp);                            \
        float e0, e1, e2, e3;                                                 \
        f2_unpack(v0, e0, e1);                                                \
        f2_unpack(v1, e2, e3);                                                \
        e0 = fabsf(e0); e1 = fabsf(e1); e2 = fabsf(e2); e3 = fabsf(e3);       \
        int gi = bm0 + i0 + (II);                                             \
        if (interior) {                                                       \
            *reinterpret_cast<float4*>(&out[(long long)gi * m + gj]) =        \
                make_float4(e0, e1, e2, e3);                                  \
        } else if (gi < n) {                                                  \
            if (gj + 0 < m) out[(long long)gi * m + gj + 0] = e0;             \
            if (gj + 1 < m) out[(long long)gi * m + gj + 1] = e1;             \
            if (gj + 2 < m) out[(long long)gi * m + gj + 2] = e2;             \
            if (gj + 3 < m) out[(long long)gi * m + gj + 3] = e3;             \
        }                                                                     \
    }

    QK_EMIT(0, a00, a01)
    QK_EMIT(1, a10, a11)
    QK_EMIT(2, a20, a21)
    QK_EMIT(3, a30, a31)
#undef QK_EMIT
}

// --- generic fallback path (runtime d): two kernels ------------------------
__global__ void qk_pre(const float* __restrict__ x, const float* __restrict__ y,
                       int n, int m, int d) {
    int i = blockIdx.x * blockDim.x + threadIdx.x;
    if (i >= n + m) return;
    const float* src = (i < n) ? x : y;
    int r = (i < n) ? i : i - n;
    int N = (i < n) ? n : m;
    float* tab = (i < n) ? g_Tx : g_Ty;
    float p = 1.0f;
    for (int k = 0; k < d; k++) {
        float s, c;
        sincosf(0.5f * src[r * d + k], &s, &c);
        if (c == 0.0f) c = 1e-30f;
        p *= c;
        tab[k * N + r] = s / c;
    }
    if (i < n) g_Px[r] = p; else g_Py[r] = p;
}

__global__ void qk_generic(float* __restrict__ out, int n, int m, int d) {
    int j = blockIdx.x * blockDim.x + threadIdx.x;
    int i = blockIdx.y;
    if (j >= m || i >= n) return;
    float p = 1.0f;
    for (int k = 0; k < d; k++)
        p = fmaf(p * g_Tx[k * n + i], g_Ty[k * m + j], p);
    out[(long long)i * m + j] = fabsf(p * g_Px[i] * g_Py[j]);
}

extern "C" void kernel_launch(void* const* d_in, const int* in_sizes, int n_in,
                              void* d_out, int out_size) {
    const float* x = (const float*)d_in[0];
    const float* y = (const float*)d_in[1];
    float* out = (float*)d_out;

    long long s0 = in_sizes[0], s1 = in_sizes[1];
    int d = (int)(0.5 + sqrt((double)s0 * (double)s1 / (double)out_size));
    if (d < 1) d = 1;
    int n = (int)(s0 / d);
    int m = (int)(s1 / d);

    if (d == 16) {
        dim3 grid((m + 63) / 64, (n + 63) / 64);
        qk_fused16<<<grid, 256>>>(out, x, y, n, m);
    } else {
        int total = n + m;
        qk_pre<<<(total + 255) / 256, 256>>>(x, y, n, m, d);
        dim3 grid((m + 255) / 256, n);
        qk_generic<<<grid, 256>>>(out, n, m, d);
    }
}